// round 16
// baseline (speedup 1.0000x reference)
#include <cuda_runtime.h>
#include <cuda_fp16.h>
#include <cstdint>
#include <math.h>

#define BB  4
#define CCH 256
#define CQ  32
#define NN  4096
#define LOG2E 1.4426950408889634f

// Scratch (device globals: no allocation allowed)
__device__ __half g_qhi[BB * NN * CQ];         // q * log2e, hi
__device__ __half g_qlo[BB * NN * CQ];         // q * log2e, lo
__device__ __half g_khi[BB * NN * CQ];
__device__ __half g_klo[BB * NN * CQ];
__device__ __half g_vh[BB * NN * CCH];         // [b][n][256] fp16
__device__ __half g_cat[BB * NN * 2 * CCH];    // [b][n][512]: [0:256)=attn, [256:512)=x^T
__device__ __half g_woh[CCH * 2 * CCH];        // Wo fp16 [o][512]
__device__ __half g_whi[320 * CCH];            // fused QKV weight hi (q rows * log2e)
__device__ __half g_wlo[320 * CCH];            // fused QKV weight lo
__device__ float  g_bias[320];                 // fused QKV bias (q rows * log2e)
__device__ __half g_xhi[BB * CCH * NN];        // x hi fp16, [b][c][n]
__device__ __half g_xlo[BB * CCH * NN];        // x lo fp16, [b][c][n]

// ---------------- PTX helpers ----------------
__device__ __forceinline__ unsigned int smaddr(const void* p) {
    return (unsigned int)__cvta_generic_to_shared(p);
}
__device__ __forceinline__ void ldsm_x4(unsigned int& r0, unsigned int& r1,
                                        unsigned int& r2, unsigned int& r3,
                                        unsigned int a) {
    asm volatile("ldmatrix.sync.aligned.m8n8.x4.shared.b16 {%0,%1,%2,%3},[%4];\n"
                 : "=r"(r0), "=r"(r1), "=r"(r2), "=r"(r3) : "r"(a));
}
__device__ __forceinline__ void ldsm_x4t(unsigned int& r0, unsigned int& r1,
                                         unsigned int& r2, unsigned int& r3,
                                         unsigned int a) {
    asm volatile("ldmatrix.sync.aligned.m8n8.x4.trans.shared.b16 {%0,%1,%2,%3},[%4];\n"
                 : "=r"(r0), "=r"(r1), "=r"(r2), "=r"(r3) : "r"(a));
}
__device__ __forceinline__ void mma_f16(float* d, const unsigned int* a,
                                        unsigned int b0, unsigned int b1) {
    asm volatile("mma.sync.aligned.m16n8k16.row.col.f32.f16.f16.f32 "
                 "{%0,%1,%2,%3},{%4,%5,%6,%7},{%8,%9},{%0,%1,%2,%3};\n"
                 : "+f"(d[0]), "+f"(d[1]), "+f"(d[2]), "+f"(d[3])
                 : "r"(a[0]), "r"(a[1]), "r"(a[2]), "r"(a[3]), "r"(b0), "r"(b1));
}
__device__ __forceinline__ unsigned int ex2h2(float a, float b) {
    half2 h = __floats2half2_rn(a, b);
    unsigned int x = *(unsigned int*)&h, r;
    asm volatile("ex2.approx.f16x2 %0, %1;\n" : "=r"(r) : "r"(x));
    return r;
}
__device__ __forceinline__ half2 hu(unsigned int x) { return *(half2*)&x; }
__device__ __forceinline__ unsigned int pack2(float a, float b) {
    half2 h = __floats2half2_rn(a, b);
    return *(unsigned int*)&h;
}
__device__ __forceinline__ void barw(int id) {
    asm volatile("bar.sync %0, 64;\n" :: "r"(id));
}
__device__ __forceinline__ void cpa16(unsigned int dst, const void* src) {
    asm volatile("cp.async.cg.shared.global [%0], [%1], 16;\n" :: "r"(dst), "l"(src));
}
__device__ __forceinline__ void cpa_commit() {
    asm volatile("cp.async.commit_group;\n");
}
__device__ __forceinline__ void cpa_wait0() {
    asm volatile("cp.async.wait_group 0;\n");
}

// ---------------------------------------------------------------------------
// Kernel 0a: fused weight prep. blocks [0,512): Wo->fp16; [512,832): QKV split.
// ---------------------------------------------------------------------------
__global__ void wprep_kernel(
    const float* __restrict__ Wo,
    const float* __restrict__ Wq, const float* __restrict__ bq,
    const float* __restrict__ Wk, const float* __restrict__ bk,
    const float* __restrict__ Wv, const float* __restrict__ bv)
{
    if (blockIdx.x < 512) {
        int i = blockIdx.x * 256 + threadIdx.x;
        g_woh[i] = __float2half(Wo[i]);
    } else {
        int i = (blockIdx.x - 512) * 256 + threadIdx.x;   // 81920 exact
        int rowi = i >> 8, col = i & 255;
        float w;
        if (rowi < 32)      w = Wq[rowi * 256 + col] * LOG2E;
        else if (rowi < 64) w = Wk[(rowi - 32) * 256 + col];
        else                w = Wv[(rowi - 64) * 256 + col];
        __half h = __float2half_rn(w);
        g_whi[i] = h;
        g_wlo[i] = __float2half_rn(w - __half2float(h));
        if (i < 320) {
            float bb;
            if (i < 32)      bb = bq[i] * LOG2E;
            else if (i < 64) bb = bk[i - 32];
            else             bb = bv[i - 64];
            g_bias[i] = bb;
        }
    }
}

// ---------------------------------------------------------------------------
// Kernel 0b: x -> cat (transposed fp16) AND x -> hi/lo fp16 (same layout)
// ---------------------------------------------------------------------------
__global__ void xpose_kernel(const float* __restrict__ x) {
    __shared__ float ts[32][33];
    const int b = blockIdx.z, n0 = blockIdx.x * 32, c0 = blockIdx.y * 32;
    const int txi = threadIdx.x, tyi = threadIdx.y;
#pragma unroll
    for (int i = 0; i < 4; i++) {
        int c = c0 + tyi + i * 8;
        const size_t off = ((size_t)b * CCH + c) * NN + n0 + txi;
        float v = x[off];
        ts[tyi + i * 8][txi] = v;
        __half h = __float2half_rn(v);
        g_xhi[off] = h;
        g_xlo[off] = __float2half_rn(v - __half2float(h));
    }
    __syncthreads();
#pragma unroll
    for (int i = 0; i < 4; i++) {
        int n = n0 + tyi + i * 8;
        g_cat[((size_t)b * NN + n) * 512 + 256 + c0 + txi] =
            __float2half(ts[txi][tyi + i * 8]);
    }
}

// ---------------------------------------------------------------------------
// Kernel 1: QKV projection via tensor cores, double-buffered, 1 sync/chunk.
// Per-buffer (27648 B): xhi[32][136h] 8704 | xlo 8704 | whi 5120 | wlo 5120
// Dynamic smem = 55296 B. Epilogue stg fp32 [64][132] aliases.
// ---------------------------------------------------------------------------
#define QB 27648
#define QKV_SMEM 55296

__global__ __launch_bounds__(256) void qkv_mma_kernel()
{
    extern __shared__ __align__(16) char smq[];

    const int b  = blockIdx.z;
    const int o0 = blockIdx.y * 64;
    const int p0 = blockIdx.x * 128;
    const int t  = threadIdx.x;
    const int lane = t & 31, wrp = t >> 5;
    const int ob  = wrp & 3;     // 16-row out band
    const int ph2 = wrp >> 2;    // 64-pix half

    float acc[8][4];
#pragma unroll
    for (int i = 0; i < 8; i++)
#pragma unroll
        for (int j = 0; j < 4; j++) acc[i][j] = 0.f;

    // issue chunk 0 into buf0
    {
        const int rowi = t >> 2, seg = t & 3;
        cpa16(smaddr(smq + 17408 + rowi * 80 + seg * 16),
              g_whi + (size_t)(o0 + rowi) * 256 + seg * 8);
        cpa16(smaddr(smq + 22528 + rowi * 80 + seg * 16),
              g_wlo + (size_t)(o0 + rowi) * 256 + seg * 8);
#pragma unroll
        for (int i = 0; i < 2; i++) {
            const int idx = t + i * 256;
            const int row = idx >> 4, ck = idx & 15;
            const size_t src = ((size_t)b * CCH + row) * NN + p0 + ck * 8;
            cpa16(smaddr(smq + row * 272 + ck * 16), g_xhi + src);
            cpa16(smaddr(smq + 8704 + row * 272 + ck * 16), g_xlo + src);
        }
        cpa_commit();
    }

    for (int kci = 0; kci < 8; kci++) {
        char* buf = smq + (kci & 1) * QB;
        char* xhi = buf;
        char* xlo = buf + 8704;
        char* whi = buf + 17408;
        char* wlo = buf + 22528;

        cpa_wait0();       // chunk kci complete (only group in flight)
        __syncthreads();   // + all warps done computing chunk kci-1

        if (kci < 7) {     // issue chunk kci+1 (overlaps compute below)
            char* nb = smq + ((kci + 1) & 1) * QB;
            const int kc1 = (kci + 1) * 32;
            const int rowi = t >> 2, seg = t & 3;
            cpa16(smaddr(nb + 17408 + rowi * 80 + seg * 16),
                  g_whi + (size_t)(o0 + rowi) * 256 + kc1 + seg * 8);
            cpa16(smaddr(nb + 22528 + rowi * 80 + seg * 16),
                  g_wlo + (size_t)(o0 + rowi) * 256 + kc1 + seg * 8);
#pragma unroll
            for (int i = 0; i < 2; i++) {
                const int idx = t + i * 256;
                const int row = idx >> 4, ck = idx & 15;
                const size_t src = ((size_t)b * CCH + kc1 + row) * NN + p0 + ck * 8;
                cpa16(smaddr(nb + row * 272 + ck * 16), g_xhi + src);
                cpa16(smaddr(nb + 8704 + row * 272 + ck * 16), g_xlo + src);
            }
            cpa_commit();
        }

        unsigned awh[2][4], awl[2][4];
#pragma unroll
        for (int ks = 0; ks < 2; ks++) {
            const int woff = (ob * 16 + (lane & 15)) * 80 + ks * 32 + ((lane >> 4) << 4);
            ldsm_x4(awh[ks][0], awh[ks][1], awh[ks][2], awh[ks][3], smaddr(whi + woff));
            ldsm_x4(awl[ks][0], awl[ks][1], awl[ks][2], awl[ks][3], smaddr(wlo + woff));
        }
#pragma unroll
        for (int ks = 0; ks < 2; ks++) {
#pragma unroll
            for (int ng = 0; ng < 4; ng++) {
                unsigned bh0, bh1, bh2, bh3, bl0, bl1, bl2, bl3;
                const int xoff = (ks * 16 + (lane & 15)) * 272
                               + ph2 * 128 + ng * 32 + ((lane >> 4) << 4);
                ldsm_x4t(bh0, bh1, bh2, bh3, smaddr(xhi + xoff));
                ldsm_x4t(bl0, bl1, bl2, bl3, smaddr(xlo + xoff));
                mma_f16(acc[ng * 2],     awh[ks], bh0, bh1);
                mma_f16(acc[ng * 2],     awl[ks], bh0, bh1);
                mma_f16(acc[ng * 2],     awh[ks], bl0, bl1);
                mma_f16(acc[ng * 2 + 1], awh[ks], bh2, bh3);
                mma_f16(acc[ng * 2 + 1], awl[ks], bh2, bh3);
                mma_f16(acc[ng * 2 + 1], awh[ks], bl2, bl3);
            }
        }
        // no trailing sync: next iteration's leading sync covers buffer reuse
    }
    __syncthreads();   // all compute done before epilogue aliases the buffers

    // ---- epilogue: bias, stage fp32, re-read transposed, write outputs ----
    float* stg = (float*)smq;   // [64][132]
    const int r0o = ob * 16 + (lane >> 2);
    const float b0 = g_bias[o0 + r0o], b1 = g_bias[o0 + r0o + 8];
#pragma unroll
    for (int j = 0; j < 8; j++) {
        const int pcol = ph2 * 64 + j * 8 + 2 * (lane & 3);
        float2 v0, v1;
        v0.x = acc[j][0] + b0; v0.y = acc[j][1] + b0;
        v1.x = acc[j][2] + b1; v1.y = acc[j][3] + b1;
        *(float2*)&stg[r0o * 132 + pcol]       = v0;
        *(float2*)&stg[(r0o + 8) * 132 + pcol] = v1;
    }
    __syncthreads();

    const int p  = t >> 1, hf = t & 1;
    const int pg = p0 + p;
    if (o0 == 0) {
        unsigned uh[16], ul[16];
#pragma unroll
        for (int i = 0; i < 16; i++) {
            float a = stg[(hf * 32 + 2 * i) * 132 + p];
            float c = stg[(hf * 32 + 2 * i + 1) * 132 + p];
            half2 h = __floats2half2_rn(a, c);
            float2 hfv = __half22float2(h);
            half2 l = __floats2half2_rn(a - hfv.x, c - hfv.y);
            uh[i] = *(unsigned*)&h;
            ul[i] = *(unsigned*)&l;
        }
        __half* dh = (hf ? g_khi : g_qhi) + ((size_t)b * NN + pg) * CQ;
        __half* dl = (hf ? g_klo : g_qlo) + ((size_t)b * NN + pg) * CQ;
#pragma unroll
        for (int i = 0; i < 4; i++) {
            ((uint4*)dh)[i] = make_uint4(uh[4*i], uh[4*i+1], uh[4*i+2], uh[4*i+3]);
            ((uint4*)dl)[i] = make_uint4(ul[4*i], ul[4*i+1], ul[4*i+2], ul[4*i+3]);
        }
    } else {
        unsigned uh[16];
#pragma unroll
        for (int i = 0; i < 16; i++) {
            float a = stg[(hf * 32 + 2 * i) * 132 + p];
            float c = stg[(hf * 32 + 2 * i + 1) * 132 + p];
            uh[i] = pack2(a, c);
        }
        __half* dv = g_vh + ((size_t)b * NN + pg) * CCH + (o0 - 64) + hf * 32;
#pragma unroll
        for (int i = 0; i < 4; i++)
            ((uint4*)dv)[i] = make_uint4(uh[4*i], uh[4*i+1], uh[4*i+2], uh[4*i+3]);
    }
}

// ---------------------------------------------------------------------------
// Kernel 2: flash attention (R11: double-buffered cp.async, 2 syncs/tile).
// ---------------------------------------------------------------------------
#define A_BUF   44032
#define A_PH    88064
#define A_RSX   97280
#define A_SCB   97792
#define ATTN_SMEM 98048

__global__ __launch_bounds__(256, 2) void attn_kernel()
{
    extern __shared__ char smd[];
    __half* ph  = (__half*)(smd + A_PH);
    float*  rsx = (float*)(smd + A_RSX);
    float*  scb = (float*)(smd + A_SCB);

    const int b    = blockIdx.y;
    const int m0   = blockIdx.x * 64;
    const int t    = threadIdx.x;
    const int lane = t & 31;
    const int wrp  = t >> 5;
    const int band = wrp & 3;
    const int ch   = wrp >> 2;
    const int bid  = band + 1;
    const int qg   = wrp & 1;
    const int cq   = wrp >> 1;

    const int row = t >> 2, c4 = t & 3;
    const int r0 = band * 16 + (lane >> 2), r1 = r0 + 8;

    {
        char* qa = smd + A_BUF + 10240;
        *((uint4*)(qa + row * 80) + c4) =
            *((const uint4*)(g_qhi + ((size_t)b * NN + m0 + row) * CQ) + c4);
        *((uint4*)(qa + 5120 + row * 80) + c4) =
            *((const uint4*)(g_qlo + ((size_t)b * NN + m0 + row) * CQ) + c4);

        cpa16(smaddr(smd + row * 80 + c4 * 16),
              g_khi + ((size_t)b * NN + row) * CQ + c4 * 8);
        cpa16(smaddr(smd + 5120 + row * 80 + c4 * 16),
              g_klo + ((size_t)b * NN + row) * CQ + c4 * 8);
        const __half* vsrc = g_vh + (size_t)b * NN * CCH;
#pragma unroll
        for (int i = 0; i < 8; i++) {
            const int idx = t + i * 256;
            const int vr = idx >> 5, vc = idx & 31;
            cpa16(smaddr(smd + 10240 + vr * 528 + vc * 16), vsrc + vr * CCH + vc * 8);
        }
        cpa_commit();
    }
    __syncthreads();

    unsigned qh[2][4], ql[2][4];
    {
        char* qa = smd + A_BUF + 10240;
        const int aoff = (band * 16 + (lane & 15)) * 80 + ((lane >> 4) << 4);
#pragma unroll
        for (int ks = 0; ks < 2; ks++) {
            ldsm_x4(qh[ks][0], qh[ks][1], qh[ks][2], qh[ks][3],
                    smaddr(qa + aoff + ks * 32));
            ldsm_x4(ql[ks][0], ql[ks][1], ql[ks][2], ql[ks][3],
                    smaddr(qa + 5120 + aoff + ks * 32));
        }
    }

    float acc[16][4];
#pragma unroll
    for (int g = 0; g < 16; g++)
#pragma unroll
        for (int j = 0; j < 4; j++) acc[g][j] = 0.f;
    float rmax0 = -INFINITY, rmax1 = -INFINITY, rsum0 = 0.f, rsum1 = 0.f;

    for (int nt = 0; nt < 64; nt++) {
        char* buf = smd + (nt & 1) * A_BUF;
        char* kh  = buf;
        char* kl  = buf + 5120;
        char* vb  = buf + 10240;

        cpa_wait0();
        __syncthreads();   // A: tile nt visible + all warps done PV of nt-1

        if (nt < 63) {
            char* nb = smd + ((nt + 1) & 1) * A_BUF;
            const int n1 = (nt + 1) * 64;
            cpa16(smaddr(nb + row * 80 + c4 * 16),
                  g_khi + ((size_t)b * NN + n1 + row) * CQ + c4 * 8);
            cpa16(smaddr(nb + 5120 + row * 80 + c4 * 16),
                  g_klo + ((size_t)b * NN + n1 + row) * CQ + c4 * 8);
            const __half* vsrc = g_vh + ((size_t)b * NN + n1) * CCH;
#pragma unroll
            for (int i = 0; i < 8; i++) {
                const int idx = t + i * 256;
                const int vr = idx >> 5, vc = idx & 31;
                cpa16(smaddr(nb + 10240 + vr * 528 + vc * 16),
                      vsrc + vr * CCH + vc * 8);
            }
            cpa_commit();
        }

        float sacc[4][4];
#pragma unroll
        for (int n = 0; n < 4; n++)
#pragma unroll
            for (int j = 0; j < 4; j++) sacc[n][j] = 0.f;
#pragma unroll
        for (int np = 0; np < 2; np++) {
#pragma unroll
            for (int ks = 0; ks < 2; ks++) {
                unsigned bh0, bh1, bh2, bh3, bl0, bl1, bl2, bl3;
                const int roff = (ch * 32 + np * 16 + ((lane >> 4) << 3) + (lane & 7)) * 80
                               + ks * 32 + (((lane >> 3) & 1) << 4);
                ldsm_x4(bh0, bh1, bh2, bh3, smaddr(kh + roff));
                ldsm_x4(bl0, bl1, bl2, bl3, smaddr(kl + roff));
                mma_f16(sacc[np * 2],     qh[ks], bh0, bh1);
                mma_f16(sacc[np * 2],     ql[ks], bh0, bh1);
                mma_f16(sacc[np * 2],     qh[ks], bl0, bl1);
                mma_f16(sacc[np * 2 + 1], qh[ks], bh2, bh3);
                mma_f16(sacc[np * 2 + 1], ql[ks], bh2, bh3);
                mma_f16(sacc[np * 2 + 1], qh[ks], bl2, bl3);
            }
        }

        float tm0 = fmaxf(fmaxf(sacc[0][0], sacc[0][1]), fmaxf(sacc[1][0], sacc[1][1]));
        float tm1 = fmaxf(fmaxf(sacc[0][2], sacc[0][3]), fmaxf(sacc[1][2], sacc[1][3]));
        tm0 = fmaxf(tm0, fmaxf(fmaxf(sacc[2][0], sacc[2][1]), fmaxf(sacc[3][0], sacc[3][1])));
        tm1 = fmaxf(tm1, fmaxf(fmaxf(sacc[2][2], sacc[2][3]), fmaxf(sacc[3][2], sacc[3][3])));
        tm0 = fmaxf(tm0, __shfl_xor_sync(0xffffffffu, tm0, 1));
        tm0 = fmaxf(tm0, __shfl_xor_sync(0xffffffffu, tm0, 2));
        tm1 = fmaxf(tm1, __shfl_xor_sync(0xffffffffu, tm1, 1));
        tm1 = fmaxf(tm1, __shfl_xor_sync(0xffffffffu, tm1, 2));
        if ((lane & 3) == 0) { rsx[ch * 64 + r0] = tm0; rsx[ch * 64 + r1] = tm1; }
        barw(bid);
        tm0 = fmaxf(tm0, rsx[(ch ^ 1) * 64 + r0]);
        tm1 = fmaxf(tm1, rsx[(ch ^ 1) * 64 + r1]);

        const float nm0 = fmaxf(rmax0, tm0), nm1 = fmaxf(rmax1, tm1);
        const float sc0 = exp2f(rmax0 - nm0), sc1 = exp2f(rmax1 - nm1);
        rmax0 = nm0; rmax1 = nm1;
        rsum0 *= sc0; rsum1 *= sc1;
        if (ch == 0 && (lane & 3) == 0) { scb[r0] = sc0; scb[r1] = sc1; }

        unsigned pr0[4], pr1[4];
#pragma unroll
        for (int nj = 0; nj < 4; nj++) {
            pr0[nj] = ex2h2(sacc[nj][0] - nm0, sacc[nj][1] - nm0);
            pr1[nj] = ex2h2(sacc[nj][2] - nm1, sacc[nj][3] - nm1);
            const int col = ch * 32 + nj * 8 + 2 * (lane & 3);
            *(half2*)(ph + r0 * 72 + col) = hu(pr0[nj]);
            *(half2*)(ph + r1 * 72 + col) = hu(pr1[nj]);
        }
        {
            float2 f0 = __half22float2(__hadd2(__hadd2(hu(pr0[0]), hu(pr0[1])),
                                               __hadd2(hu(pr0[2]), hu(pr0[3]))));
            float2 f1 = __half22float2(__hadd2(__hadd2(hu(pr1[0]), hu(pr1[1])),
                                               __hadd2(hu(pr1[2]), hu(pr1[3]))));
            rsum0 += f0.x + f0.y;
            rsum1 += f1.x + f1.y;
        }
        __syncthreads();   // B: P + scb ready block-wide

        {
            const int rb = qg * 32 + (lane >> 2);
            const float s0 = scb[rb],      s1 = scb[rb + 8];
            const float s2 = scb[rb + 16], s3 = scb[rb + 24];
            const bool skip = __all_sync(0xffffffffu,
                (s0 == 1.f) && (s1 == 1.f) && (s2 == 1.f) && (s3 == 1.f));
            if (!skip) {
#pragma unroll
                for (int nj = 0; nj < 8; nj++) {
                    acc[nj][0] *= s0; acc[nj][1] *= s0;
                    acc[nj][2] *= s1; acc[nj][3] *= s1;
                    acc[8 + nj][0] *= s2; acc[8 + nj][1] *= s2;
                    acc[8 + nj][2] *= s3; acc[8 + nj][3] *= s3;
                }
            }
#pragma unroll
            for (int ks = 0; ks < 4; ks++) {
                unsigned pf0[4], pf1[4];
                const int pcol = ks * 32 + ((lane >> 4) << 4);
                ldsm_x4(pf0[0], pf0[1], pf0[2], pf0[3],
                    smaddr((char*)ph + (qg * 32 + (lane & 15)) * 144 + pcol));
                ldsm_x4(pf1[0], pf1[1], pf1[2], pf1[3],
                    smaddr((char*)ph + (qg * 32 + 16 + (lane & 15)) * 144 + pcol));
                const int vrow = (ks * 16 + (lane & 15)) * 528
                               + cq * 128 + ((lane >> 4) << 4);
#pragma unroll
                for (int cc = 0; cc < 4; cc++) {
                    unsigned v0, v1, v2, v3;
                    ldsm_x4t(v0, v1, v2, v3, smaddr(vb + vrow + cc * 32));
                    mma_f16(acc[cc * 2],         pf0, v0, v1);
                    mma_f16(acc[cc * 2 + 1],     pf0, v2, v3);
                    mma_f16(acc[8 + cc * 2],     pf1, v0, v1);
                    mma_f16(acc[8 + cc * 2 + 1], pf1, v2, v3);
                }
            }
        }
    }

    rsum0 += __shfl_xor_sync(0xffffffffu, rsum0, 1);
    rsum0 += __shfl_xor_sync(0xffffffffu, rsum0, 2);
    rsum1 += __shfl_xor_sync(0xffffffffu, rsum1, 1);
    rsum1 += __shfl_xor_sync(0xffffffffu, rsum1, 2);
    if ((lane & 3) == 0) { rsx[ch * 64 + r0] = rsum0; rsx[ch * 64 + r1] = rsum1; }
    __syncthreads();
    if (ch == 0 && (lane & 3) == 0) {
        scb[r0] = 1.f / (rsum0 + rsx[64 + r0]);
        scb[r1] = 1.f / (rsum1 + rsx[64 + r1]);
    }
    __syncthreads();

    const int rb = qg * 32 + (lane >> 2);
    const float i0 = scb[rb],      i1 = scb[rb + 8];
    const float i2 = scb[rb + 16], i3 = scb[rb + 24];
#pragma unroll
    for (int nj = 0; nj < 8; nj++) {
        const int col = cq * 64 + nj * 8 + 2 * (lane & 3);
        *(half2*)(g_cat + ((size_t)b * NN + m0 + rb) * 512 + col) =
            __floats2half2_rn(acc[nj][0] * i0, acc[nj][1] * i0);
        *(half2*)(g_cat + ((size_t)b * NN + m0 + rb + 8) * 512 + col) =
            __floats2half2_rn(acc[nj][2] * i1, acc[nj][3] * i1);
        *(half2*)(g_cat + ((size_t)b * NN + m0 + rb + 16) * 512 + col) =
            __floats2half2_rn(acc[8 + nj][0] * i2, acc[8 + nj][1] * i2);
        *(half2*)(g_cat + ((size_t)b * NN + m0 + rb + 24) * 512 + col) =
            __floats2half2_rn(acc[8 + nj][2] * i3, acc[8 + nj][3] * i3);
    }
}

// ---------------------------------------------------------------------------
// Kernel 3: output projection via mma, double-buffered, 1 sync/chunk.
// Per-buffer (27648 B): As[64][72h] 9216 | Bs[128][72h] 18432. Dyn smem 55296.
// ---------------------------------------------------------------------------
#define OB 27648
#define OUT_SMEM 55296

__global__ __launch_bounds__(256) void outproj_kernel(
    const float* __restrict__ bo, float* __restrict__ y)
{
    extern __shared__ __align__(16) char smo[];

    const int b  = blockIdx.z;
    const int o0 = blockIdx.y * 64;
    const int m0 = blockIdx.x * 128;
    const int t  = threadIdx.x;
    const int lane = t & 31, wrp = t >> 5;
    const int ob = (wrp & 3) * 16;
    const int mh = (wrp >> 2) * 64;

    float acc[8][4];
#pragma unroll
    for (int i = 0; i < 8; i++)
#pragma unroll
        for (int j = 0; j < 4; j++) acc[i][j] = 0.f;

    // issue chunk 0 into buf0
    {
#pragma unroll
        for (int i = 0; i < 2; i++) {
            const int idx = t + i * 256;
            const int rowi = idx >> 3, c16 = idx & 7;
            cpa16(smaddr(smo + rowi * 144 + c16 * 16),
                  g_woh + (size_t)(o0 + rowi) * 512 + c16 * 8);
        }
#pragma unroll
        for (int i = 0; i < 4; i++) {
            const int idx = t + i * 256;
            const int rowi = idx >> 3, c16 = idx & 7;
            cpa16(smaddr(smo + 9216 + rowi * 144 + c16 * 16),
                  g_cat + ((size_t)b * NN + m0 + rowi) * 512 + c16 * 8);
        }
        cpa_commit();
    }

    for (int kci = 0; kci < 8; kci++) {
        char* buf = smo + (kci & 1) * OB;
        __half* As = (__half*)buf;
        __half* Bs = (__half*)(buf + 9216);

        cpa_wait0();
        __syncthreads();

        if (kci < 7) {
            char* nb = smo + ((kci + 1) & 1) * OB;
            const int k1 = (kci + 1) * 64;
#pragma unroll
            for (int i = 0; i < 2; i++) {
                const int idx = t + i * 256;
                const int rowi = idx >> 3, c16 = idx & 7;
                cpa16(smaddr(nb + rowi * 144 + c16 * 16),
                      g_woh + (size_t)(o0 + rowi) * 512 + k1 + c16 * 8);
            }
#pragma unroll
            for (int i = 0; i < 4; i++) {
                const int idx = t + i * 256;
                const int rowi = idx >> 3, c16 = idx & 7;
                cpa16(smaddr(nb + 9216 + rowi * 144 + c16 * 16),
                      g_cat + ((size_t)b * NN + m0 + rowi) * 512 + k1 + c16 * 8);
            }
            cpa_commit();
        }

        unsigned int af[4][4];
#pragma unroll
        for (int k4 = 0; k4 < 4; k4++) {
            unsigned int a = smaddr(As + (ob + (lane & 15)) * 72 + k4 * 16 + (lane >> 4) * 8);
            ldsm_x4(af[k4][0], af[k4][1], af[k4][2], af[k4][3], a);
        }
#pragma unroll
        for (int pr = 0; pr < 4; pr++) {
#pragma unroll
            for (int k4 = 0; k4 < 4; k4++) {
                unsigned int b0, b1, b2, b3;
                unsigned int a = smaddr(Bs + (mh + pr * 16 + (lane >> 4) * 8 + (lane & 7)) * 72
                                           + k4 * 16 + ((lane >> 3) & 1) * 8);
                ldsm_x4(b0, b1, b2, b3, a);
                mma_f16(acc[pr * 2],     af[k4], b0, b1);
                mma_f16(acc[pr * 2 + 1], af[k4], b2, b3);
            }
        }
        // no trailing sync: next iteration's leading sync covers buffer reuse
    }

    const int orow = o0 + ob + (lane >> 2);
    const float bi0 = bo[orow], bi1 = bo[orow + 8];
#pragma unroll
    for (int chn = 0; chn < 8; chn++) {
        const int m = m0 + mh + chn * 8 + (lane & 3) * 2;
        float2 v0, v1;
        v0.x = acc[chn][0] + bi0; v0.y = acc[chn][1] + bi0;
        v1.x = acc[chn][2] + bi1; v1.y = acc[chn][3] + bi1;
        *(float2*)(y + ((size_t)b * CCH + orow)     * NN + m) = v0;
        *(float2*)(y + ((size_t)b * CCH + orow + 8) * NN + m) = v1;
    }
}

// ---------------------------------------------------------------------------
extern "C" void kernel_launch(void* const* d_in, const int* in_sizes, int n_in,
                              void* d_out, int out_size)
{
    const float* x  = (const float*)d_in[0];
    const float* Wq = (const float*)d_in[1];
    const float* bq = (const float*)d_in[2];
    const float* Wk = (const float*)d_in[3];
    const float* bk = (const float*)d_in[4];
    const float* Wv = (const float*)d_in[5];
    const float* bv = (const float*)d_in[6];
    const float* Wo = (const float*)d_in[7];
    const float* bo = (const float*)d_in[8];
    float* y = (float*)d_out;

    cudaFuncSetAttribute(attn_kernel,
                         cudaFuncAttributeMaxDynamicSharedMemorySize, ATTN_SMEM);
    cudaFuncSetAttribute(qkv_mma_kernel,
                         cudaFuncAttributeMaxDynamicSharedMemorySize, QKV_SMEM);
    cudaFuncSetAttribute(outproj_kernel,
                         cudaFuncAttributeMaxDynamicSharedMemorySize, OUT_SMEM);

    wprep_kernel<<<832, 256>>>(Wo, Wq, bq, Wk, bk, Wv, bv);
    xpose_kernel<<<dim3(128, 8, BB), dim3(32, 8)>>>(x);
    qkv_mma_kernel<<<dim3(32, 5, BB), 256, QKV_SMEM>>>();
    attn_kernel<<<dim3(64, BB), 256, ATTN_SMEM>>>();
    outproj_kernel<<<dim3(32, 4, BB), 256, OUT_SMEM>>>(bo, y);
}